// round 15
// baseline (speedup 1.0000x reference)
#include <cuda_runtime.h>
#include <cuda_bf16.h>
#include <cuda_fp16.h>

typedef unsigned int u32;
typedef unsigned char u8;
typedef unsigned short u16;

#define ROWS 65536
#define NBSTRIDE 33792
#define MIDB 1088              // padded concat stride (1056 data + 32 zeros)
#define MIN_VAL (-10000000.0f)
#define GRID_P 304

// ---------------- persistent scratch (BSS, zero-init) ----------------
__device__ u8    g_hc [(size_t)ROWS * MIDB];   // fp8: [x(32) | h1..h4 | zeros]
__device__ u8    g_agg[(size_t)ROWS * 256];    // compact aggregated input (e4m3)
__device__ u8    g_w0t[256 * 64];              // W0^T [N=256][K=64], k>=32 zero
__device__ u8    g_wst[3][256 * 256];          // Ws^T fp8
__device__ u8    g_w1t[(size_t)512 * 1088];    // W1^T fp8, k>=1056 zero
__device__ float g_part[2 * ROWS];             // head partial dots per N-half
__device__ float g_sc[512], g_sh[512];         // folded BN scale/shift
__device__ u32   g_ctr[8];                     // dynamic tile counters

// ---------------- helpers ----------------
__device__ __forceinline__ u32 s2u(const void* p){
    u32 a;
    asm("{ .reg .u64 t; cvta.to.shared.u64 t, %1; cvt.u32.u64 %0, t; }" : "=r"(a) : "l"(p));
    return a;
}
__device__ __forceinline__ void cpa16(u32 dst, const void* src){
    asm volatile("cp.async.cg.shared.global [%0], [%1], 16;" :: "r"(dst), "l"(src));
}
#define CP_COMMIT() asm volatile("cp.async.commit_group;" ::: "memory")
#define CP_WAIT(n)  asm volatile("cp.async.wait_group %0;" :: "n"(n) : "memory")

__device__ __forceinline__ void mma_fp8_h(u32* c, const u32* a, const u32* b){
    asm volatile("mma.sync.aligned.m16n8k32.row.col.f16.e4m3.e4m3.f16 "
        "{%0,%1}, {%2,%3,%4,%5}, {%6,%7}, {%0,%1};"
        : "+r"(c[0]), "+r"(c[1])
        : "r"(a[0]), "r"(a[1]), "r"(a[2]), "r"(a[3]), "r"(b[0]), "r"(b[1]));
}
#define LDSM4(r0, r1, r2, r3, addr) \
    asm volatile("ldmatrix.sync.aligned.m8n8.x4.shared.b16 {%0,%1,%2,%3}, [%4];" \
        : "=r"(r0), "=r"(r1), "=r"(r2), "=r"(r3) : "r"(addr))

__device__ __forceinline__ u16 pk8(float lo, float hi){
    u16 t;
    asm("cvt.rn.satfinite.e4m3x2.f32 %0, %1, %2;" : "=h"(t) : "f"(hi), "f"(lo));
    return t;
}
__device__ __forceinline__ u8 cvt1(float v){ return (u8)(pk8(v, 0.f) & 0xff); }
__device__ __forceinline__ float2 h2f(u32 h){
    return __half22float2(*reinterpret_cast<__half2*>(&h));
}
__device__ __forceinline__ void hacc_fp8x4(u32& a0, u32& a1, u32 v){
    u32 f0, f1;
    asm("cvt.rn.f16x2.e4m3x2 %0, %1;" : "=r"(f0) : "h"((u16)(v & 0xffff)));
    asm("cvt.rn.f16x2.e4m3x2 %0, %1;" : "=r"(f1) : "h"((u16)(v >> 16)));
    asm("add.rn.f16x2 %0, %0, %1;" : "+r"(a0) : "r"(f0));
    asm("add.rn.f16x2 %0, %0, %1;" : "+r"(a1) : "r"(f1));
}
__device__ __forceinline__ u32 pack2h(u32 h0, u32 h1){
    u16 a, b;
    asm("cvt.rn.satfinite.e4m3x2.f16x2 %0, %1;" : "=h"(a) : "r"(h0));
    asm("cvt.rn.satfinite.e4m3x2.f16x2 %0, %1;" : "=h"(b) : "r"(h1));
    return (u32)a | ((u32)b << 16);
}

// ---------------- merged prep kernel ----------------
__global__ void prep_all(const float* __restrict__ W0, const float* __restrict__ Ws,
                         const float* __restrict__ W1,
                         const float* __restrict__ bn_g, const float* __restrict__ bn_b,
                         const float* __restrict__ bn_m, const float* __restrict__ bn_v){
    int blk = blockIdx.x, tid = threadIdx.x;
    if (blk < 32){
        int i = blk * 256 + tid;
        int n = i >> 5, k = i & 31;
        g_w0t[n * 64 + k] = cvt1(W0[k * 256 + n]);
    } else if (blk < 800){
        int i = (blk - 32) * 256 + tid;
        int l = i >> 16, r = i & 65535;
        int n = r >> 8, k = r & 255;
        g_wst[l][n * 256 + k] = cvt1(Ws[l * 65536 + k * 256 + n]);
    } else if (blk < 2976){
        int i = (blk - 800) * 256 + tid;
        int n = i / 1088, k = i - n * 1088;
        g_w1t[i] = (k < 1056) ? cvt1(W1[k * 512 + n]) : (u8)0;
    } else {
        int i = (blk - 2976) * 256 + tid;
        if (i < 512){
            float sc = bn_g[i] * rsqrtf(bn_v[i] + 1e-5f);
            g_sc[i] = sc;
            g_sh[i] = bn_b[i] - bn_m[i] * sc;
        }
    }
}

__global__ void xcvt(const float* __restrict__ obs){
    int q = blockIdx.x * 256 + threadIdx.x;
    int row = q >> 2, j = q & 3;
    int b = row >> 10, n = row & 1023;
    const float4* s = reinterpret_cast<const float4*>(obs + (size_t)b * NBSTRIDE + 1024 + n * 32 + j * 8);
    float4 a = s[0], c = s[1];
    u32 w0 = (u32)pk8(a.x, a.y) | ((u32)pk8(a.z, a.w) << 16);
    u32 w1 = (u32)pk8(c.x, c.y) | ((u32)pk8(c.z, c.w) << 16);
    *reinterpret_cast<uint2*>(g_hc + (size_t)row * MIDB + j * 8) = make_uint2(w0, w1);
}

// ---------------- halo-staged 4-neighbor aggregation ----------------
// CTA = (image b, band of 8 grid rows). Halo = 10 grid rows = 320 consecutive node-rows
// staged via cp.async into smem (pitch SRCW+16, conflict-free). Out-of-image rows zeroed.
// Each thread owns one output node; loops over SRCW/16 segments via LDS.
template<int SRCW, int KW>
__global__ void __launch_bounds__(256, 2)
agg_halo(const u8* __restrict__ src){
    extern __shared__ char sm[];
    constexpr int PH = SRCW + 16;
    constexpr int SEGS = SRCW / 16;
    const u32 sb = s2u(sm);
    const int tid = threadIdx.x;
    const int b = blockIdx.x >> 2, band = blockIdx.x & 3;
    const int r0 = band * 8;
    const int base_node = (b << 10) + (r0 - 1) * 32;   // first halo node (may be -32)

    // stage halo: 320 rows x SEGS segs
    for (int idx = tid; idx < 320 * SEGS; idx += 256){
        int hrow = idx / SEGS, seg = idx - hrow * SEGS;
        bool valid = !(band == 0 && hrow < 32) && !(band == 3 && hrow >= 288);
        u32 dst = sb + (u32)(hrow * PH + seg * 16);
        if (valid)
            cpa16(dst, src + (size_t)(base_node + hrow) * MIDB + seg * 16);
        else
            *reinterpret_cast<uint4*>(sm + (hrow * PH + seg * 16)) = make_uint4(0u, 0u, 0u, 0u);
    }
    CP_COMMIT();
    CP_WAIT(0);
    __syncthreads();

    const int on = tid;                 // local output node 0..255
    const int c = on & 31;
    const int orow = (b << 10) + r0 * 32 + on;
    const char* hb = sm + (size_t)(on + 32) * PH;
    u8* drow = g_agg + (size_t)orow * KW;
#pragma unroll
    for (int seg = 0; seg < SEGS; seg++){
        u32 s[8];
#pragma unroll
        for (int e = 0; e < 8; e++) s[e] = 0u;
        uint4 v;
        v = *reinterpret_cast<const uint4*>(hb - 32 * PH + seg * 16);   // up (zeroed if OOB)
        hacc_fp8x4(s[0], s[1], v.x); hacc_fp8x4(s[2], s[3], v.y);
        hacc_fp8x4(s[4], s[5], v.z); hacc_fp8x4(s[6], s[7], v.w);
        v = *reinterpret_cast<const uint4*>(hb + 32 * PH + seg * 16);   // down
        hacc_fp8x4(s[0], s[1], v.x); hacc_fp8x4(s[2], s[3], v.y);
        hacc_fp8x4(s[4], s[5], v.z); hacc_fp8x4(s[6], s[7], v.w);
        if (c > 0){
            v = *reinterpret_cast<const uint4*>(hb - PH + seg * 16);    // left
            hacc_fp8x4(s[0], s[1], v.x); hacc_fp8x4(s[2], s[3], v.y);
            hacc_fp8x4(s[4], s[5], v.z); hacc_fp8x4(s[6], s[7], v.w);
        }
        if (c < 31){
            v = *reinterpret_cast<const uint4*>(hb + PH + seg * 16);    // right
            hacc_fp8x4(s[0], s[1], v.x); hacc_fp8x4(s[2], s[3], v.y);
            hacc_fp8x4(s[4], s[5], v.z); hacc_fp8x4(s[6], s[7], v.w);
        }
        *reinterpret_cast<uint4*>(drow + seg * 16) =
            make_uint4(pack2h(s[0], s[1]), pack2h(s[2], s[3]),
                       pack2h(s[4], s[5]), pack2h(s[6], s[7]));
    }
#pragma unroll
    for (int seg = SEGS; seg < KW / 16; seg++)
        *reinterpret_cast<uint4*>(drow + seg * 16) = make_uint4(0u, 0u, 0u, 0u);
}

// ---------------- B-resident persistent layer GEMM + LN ----------------
// Tile 128x256, 256 thr, 8 warps (wm=wid&1, wn=wid>>1), warp tile 64x64, occ 2.
// B^T (256 x KFULL) loaded ONCE into smem (pitch BP, 16-stagger). A streamed from g_agg
// in 64-col chunks, 3-stage cp.async. Epilogue: bias+LN+ReLU -> e4m3 into g_hc.
// SMEM: B @0 (BBYTES), A stages @BBYTES (3x10240), red @BBYTES+30720, musd +4096.
template<int KFULL, int BP, int BBYTES>
__global__ void __launch_bounds__(256, 2)
gemm_res(const u8* __restrict__ A, const u8* __restrict__ Bt, int slot,
         const float* __restrict__ bias, const float* __restrict__ gamma,
         const float* __restrict__ beta, u8* __restrict__ outp)
{
    extern __shared__ char sm[];
    __shared__ u32 s_tile;
    const u32 sb = s2u(sm);
    const int tid  = threadIdx.x;
    const int lane = tid & 31, wid = tid >> 5;
    const int wm = wid & 1, wn = wid >> 1;
    constexpr int NC = KFULL / 64;
    constexpr int SEGS = KFULL / 16;

    // one-time B load (group completes before first mma via WAIT(2) chain)
    for (int idx = tid; idx < 256 * SEGS; idx += 256){
        int n = idx / SEGS, seg = idx - n * SEGS;
        cpa16(sb + (u32)(n * BP + seg * 16), Bt + (size_t)n * KFULL + seg * 16);
    }
    CP_COMMIT();

    auto cpA = [&](int row0, int kc, int stg){
#pragma unroll
        for (int i = 0; i < 2; i++){
            int q = tid + 256 * i;
            int r = q >> 2, seg = q & 3;
            cpa16(sb + (u32)(BBYTES + stg * 10240 + r * 80 + seg * 16),
                  A + (size_t)(row0 + r) * KFULL + kc * 64 + seg * 16);
        }
    };

    for (;;){
        __syncthreads();
        if (tid == 0) s_tile = atomicAdd(&g_ctr[slot], 1u);
        __syncthreads();
        const u32 t = s_tile;
        if (t >= 512u) break;
        const int row0 = (int)t << 7;

        u32 acc[4][8][2];
#pragma unroll
        for (int mt = 0; mt < 4; mt++)
#pragma unroll
            for (int nt = 0; nt < 8; nt++){ acc[mt][nt][0] = 0u; acc[mt][nt][1] = 0u; }

#pragma unroll
        for (int p = 0; p < 2; p++){
            if (p < NC) cpA(row0, p, p);
            CP_COMMIT();
        }

        for (int kc = 0; kc < NC; kc++){
            if (kc + 2 < NC) cpA(row0, kc + 2, (kc + 2) % 3);
            CP_COMMIT();
            CP_WAIT(2);
            __syncthreads();

            const u32 Ab = sb + (u32)(BBYTES + (kc % 3) * 10240);
#pragma unroll
            for (int s = 0; s < 2; s++){
                u32 a[4][4], b[8][2];
#pragma unroll
                for (int mt = 0; mt < 4; mt++){
                    u32 addr = Ab + (u32)((wm * 64 + mt * 16 + (lane & 7) + ((lane >> 3) & 1) * 8) * 80
                                          + s * 32 + (lane >> 4) * 16);
                    LDSM4(a[mt][0], a[mt][1], a[mt][2], a[mt][3], addr);
                }
#pragma unroll
                for (int np = 0; np < 4; np++){
                    u32 addr = sb + (u32)((wn * 64 + (np * 2 + (lane >> 4)) * 8 + (lane & 7)) * BP
                                          + kc * 64 + s * 32 + ((lane >> 3) & 1) * 16);
                    LDSM4(b[np * 2][0], b[np * 2][1], b[np * 2 + 1][0], b[np * 2 + 1][1], addr);
                }
#pragma unroll
                for (int mt = 0; mt < 4; mt++)
#pragma unroll
                    for (int nt = 0; nt < 8; nt++)
                        mma_fp8_h(acc[mt][nt], a[mt], b[nt]);
            }
        }
        __syncthreads();

        // LN epilogue (two passes over acc; no fp32 stash)
        const int cbase = wn * 64 + (lane & 3) * 2;
        float s1[4][2], s2[4][2];
#pragma unroll
        for (int mt = 0; mt < 4; mt++){ s1[mt][0]=0.f; s1[mt][1]=0.f; s2[mt][0]=0.f; s2[mt][1]=0.f; }
#pragma unroll
        for (int mt = 0; mt < 4; mt++)
#pragma unroll
            for (int nt = 0; nt < 8; nt++){
                int c = cbase + nt * 8;
                float b0 = __ldg(bias + c), b1v = __ldg(bias + c + 1);
                float2 p0 = h2f(acc[mt][nt][0]);
                float2 p1 = h2f(acc[mt][nt][1]);
                float v0 = p0.x + b0, v1 = p0.y + b1v;
                float v2 = p1.x + b0, v3 = p1.y + b1v;
                s1[mt][0] += v0 + v1; s2[mt][0] = fmaf(v0, v0, fmaf(v1, v1, s2[mt][0]));
                s1[mt][1] += v2 + v3; s2[mt][1] = fmaf(v2, v2, fmaf(v3, v3, s2[mt][1]));
            }
#pragma unroll
        for (int o = 1; o <= 2; o <<= 1)
#pragma unroll
            for (int mt = 0; mt < 4; mt++)
#pragma unroll
                for (int h = 0; h < 2; h++){
                    s1[mt][h] += __shfl_xor_sync(0xffffffffu, s1[mt][h], o);
                    s2[mt][h] += __shfl_xor_sync(0xffffffffu, s2[mt][h], o);
                }
        float2* red = reinterpret_cast<float2*>(sm + BBYTES + 30720);
        if ((lane & 3) == 0){
#pragma unroll
            for (int mt = 0; mt < 4; mt++)
#pragma unroll
                for (int h = 0; h < 2; h++){
                    int r = wm * 64 + mt * 16 + (lane >> 2) + 8 * h;
                    red[r * 4 + wn] = make_float2(s1[mt][h], s2[mt][h]);
                }
        }
        __syncthreads();
        float2* musd = reinterpret_cast<float2*>(sm + BBYTES + 30720 + 4096);
        if (tid < 128){
            float S1 = 0.f, S2 = 0.f;
#pragma unroll
            for (int w = 0; w < 4; w++){ float2 v = red[tid * 4 + w]; S1 += v.x; S2 += v.y; }
            float mu = S1 * (1.f / 256.f);
            float rstd = rsqrtf(fmaf(-mu, mu, S2 * (1.f / 256.f)) + 1e-5f);
            musd[tid] = make_float2(mu, rstd);
        }
        __syncthreads();
#pragma unroll
        for (int mt = 0; mt < 4; mt++)
#pragma unroll
            for (int h = 0; h < 2; h++){
                int r = wm * 64 + mt * 16 + (lane >> 2) + 8 * h;
                float2 ms = musd[r];
                u8* orow = outp + (size_t)(row0 + r) * MIDB;
#pragma unroll
                for (int nt = 0; nt < 8; nt++){
                    int c = cbase + nt * 8;
                    float2 p = (h == 0) ? h2f(acc[mt][nt][0]) : h2f(acc[mt][nt][1]);
                    float v0 = p.x + __ldg(bias + c);
                    float v1 = p.y + __ldg(bias + c + 1);
                    float o0 = fmaxf(fmaf((v0 - ms.x) * ms.y, __ldg(gamma + c),     __ldg(beta + c)),     0.f);
                    float o1 = fmaxf(fmaf((v1 - ms.x) * ms.y, __ldg(gamma + c + 1), __ldg(beta + c + 1)), 0.f);
                    *reinterpret_cast<u16*>(orow + c) = pk8(o0, o1);
                }
            }
    }
}

// ---------------- head: tile 128x256, 3-stage, fused BN/ReLU/W2 (R13, proven) ----
#define SMTOT_H 92160
__global__ void __launch_bounds__(256, 2)
gemm_head(const u8* __restrict__ A, const u8* __restrict__ Bt,
          const float* __restrict__ b1, const float* __restrict__ W2)
{
    extern __shared__ char sm[];
    __shared__ u32 s_tile;
    const u32 sb = s2u(sm);
    const int tid  = threadIdx.x;
    const int lane = tid & 31, wid = tid >> 5;
    const int wm = wid & 1, wn = wid >> 1;
    constexpr int NC = 17;

    for (;;){
        __syncthreads();
        if (tid == 0) s_tile = atomicAdd(&g_ctr[4], 1u);
        __syncthreads();
        const u32 t = s_tile;
        if (t >= 1024u) break;

        const int row0  = (int)(t >> 1) << 7;
        const int ncol0 = (int)(t & 1) << 8;
        const u8* Bp = Bt + (size_t)ncol0 * 1088;

        auto cpA = [&](int kc, int stg){
#pragma unroll
            for (int i = 0; i < 2; i++){
                int q = tid + 256 * i;
                int r = q >> 2, seg = q & 3;
                cpa16(sb + (u32)stg * 30720u + (u32)(r * 80 + seg * 16),
                      A + (size_t)(row0 + r) * MIDB + kc * 64 + seg * 16);
            }
        };
        auto cpB = [&](int kc, int stg){
#pragma unroll
            for (int i = 0; i < 4; i++){
                int q = tid + 256 * i;
                int n = q >> 2, seg = q & 3;
                cpa16(sb + (u32)stg * 30720u + 10240u + (u32)(n * 80 + seg * 16),
                      Bp + (size_t)n * 1088 + kc * 64 + seg * 16);
            }
        };

        u32 acc[4][8][2];
#pragma unroll
        for (int mt = 0; mt < 4; mt++)
#pragma unroll
            for (int nt = 0; nt < 8; nt++){ acc[mt][nt][0] = 0u; acc[mt][nt][1] = 0u; }

#pragma unroll
        for (int p = 0; p < 2; p++){
            cpA(p, p); cpB(p, p);
            CP_COMMIT();
        }

        for (int kc = 0; kc < NC; kc++){
            if (kc + 2 < NC){
                int stg2 = (kc + 2) % 3;
                cpA(kc + 2, stg2); cpB(kc + 2, stg2);
            }
            CP_COMMIT();
            CP_WAIT(2);
            __syncthreads();

            const u32 Ab = sb + (u32)(kc % 3) * 30720u;
            const u32 Bb = Ab + 10240u;
#pragma unroll
            for (int s = 0; s < 2; s++){
                u32 a[4][4], b[8][2];
#pragma unroll
                for (int mt = 0; mt < 4; mt++){
                    u32 addr = Ab + (u32)((wm * 64 + mt * 16 + (lane & 7) + ((lane >> 3) & 1) * 8) * 80
                                          + s * 32 + (lane >> 4) * 16);
                    LDSM4(a[mt][0], a[mt][1], a[mt][2], a[mt][3], addr);
                }
#pragma unroll
                for (int np = 0; np < 4; np++){
                    u32 addr = Bb + (u32)((wn * 64 + (np * 2 + (lane >> 4)) * 8 + (lane & 7)) * 80
                                          + s * 32 + ((lane >> 3) & 1) * 16);
                    LDSM4(b[np * 2][0], b[np * 2][1], b[np * 2 + 1][0], b[np * 2 + 1][1], addr);
                }
#pragma unroll
                for (int mt = 0; mt < 4; mt++)
#pragma unroll
                    for (int nt = 0; nt < 8; nt++)
                        mma_fp8_h(acc[mt][nt], a[mt], b[nt]);
            }
        }
        __syncthreads();

        const int cbase = wn * 64 + (lane & 3) * 2;
        float* part = reinterpret_cast<float*>(sm + 61440);
#pragma unroll
        for (int mt = 0; mt < 4; mt++)
#pragma unroll
            for (int h = 0; h < 2; h++){
                int r = wm * 64 + mt * 16 + (lane >> 2) + 8 * h;
                float s = 0.f;
#pragma unroll
                for (int nt = 0; nt < 8; nt++){
                    int c  = cbase + nt * 8;
                    int gc = ncol0 + c;
                    float2 p = (h == 0) ? h2f(acc[mt][nt][0]) : h2f(acc[mt][nt][1]);
                    float v0 = p.x + __ldg(b1 + gc);
                    float v1 = p.y + __ldg(b1 + gc + 1);
                    float t0 = fmaxf(fmaf(v0, g_sc[gc],     g_sh[gc]),     0.f);
                    float t1 = fmaxf(fmaf(v1, g_sc[gc + 1], g_sh[gc + 1]), 0.f);
                    s = fmaf(t0, __ldg(W2 + gc), s);
                    s = fmaf(t1, __ldg(W2 + gc + 1), s);
                }
                s += __shfl_xor_sync(0xffffffffu, s, 1);
                s += __shfl_xor_sync(0xffffffffu, s, 2);
                if ((lane & 3) == 0) part[r * 4 + wn] = s;
            }
        __syncthreads();
        if (tid < 128){
            float S = part[tid * 4] + part[tid * 4 + 1] + part[tid * 4 + 2] + part[tid * 4 + 3];
            g_part[(size_t)(t & 1) * ROWS + row0 + tid] = S;
        }
    }
}

// ---------------- tail: combine partials, +b2, mask; reset counters ----------------
__global__ void mask_kernel(const float* __restrict__ obs, const float* __restrict__ b2,
                            float* __restrict__ out){
    int idx = blockIdx.x * 256 + threadIdx.x;
    int b = idx >> 10, n = idx & 1023;
    float y = g_part[idx] + g_part[ROWS + idx] + b2[0];
    out[idx] = (obs[(size_t)b * NBSTRIDE + n] != 0.f) ? y : MIN_VAL;
    if (idx < 8) g_ctr[idx] = 0u;
}

// ---------------- launch ----------------
extern "C" void kernel_launch(void* const* d_in, const int* in_sizes, int n_in,
                              void* d_out, int out_size) {
    const float* obs  = (const float*)d_in[0];
    const float* W0   = (const float*)d_in[3];
    const float* b0   = (const float*)d_in[4];
    const float* g0   = (const float*)d_in[5];
    const float* be0  = (const float*)d_in[6];
    const float* Ws   = (const float*)d_in[7];
    const float* bs   = (const float*)d_in[8];
    const float* gs   = (const float*)d_in[9];
    const float* bes  = (const float*)d_in[10];
    const float* W1   = (const float*)d_in[11];
    const float* b1   = (const float*)d_in[12];
    const float* bn_g = (const float*)d_in[13];
    const float* bn_b = (const float*)d_in[14];
    const float* bn_m = (const float*)d_in[15];
    const float* bn_v = (const float*)d_in[16];
    const float* W2   = (const float*)d_in[17];
    const float* b2   = (const float*)d_in[18];
    float* out = (float*)d_out;

    u8 *hc, *agg, *w0t, *wst, *w1t;
    cudaGetSymbolAddress((void**)&hc,  g_hc);
    cudaGetSymbolAddress((void**)&agg, g_agg);
    cudaGetSymbolAddress((void**)&w0t, g_w0t);
    cudaGetSymbolAddress((void**)&wst, g_wst);
    cudaGetSymbolAddress((void**)&w1t, g_w1t);

    // smem sizes: layer0 gemm: B 20480 + A 30720 + red/musd 5120 = 56320
    //             layer  gemm: B 69632 + A 30720 + red/musd 5120 = 105472
    //             agg: layer0 320*48 = 15360; layers 320*272 = 87040
    cudaFuncSetAttribute(agg_halo<32, 64>,            cudaFuncAttributeMaxDynamicSharedMemorySize, 15360);
    cudaFuncSetAttribute(agg_halo<256, 256>,          cudaFuncAttributeMaxDynamicSharedMemorySize, 87040);
    cudaFuncSetAttribute(gemm_res<64,  80,  20480>,   cudaFuncAttributeMaxDynamicSharedMemorySize, 56320);
    cudaFuncSetAttribute(gemm_res<256, 272, 69632>,   cudaFuncAttributeMaxDynamicSharedMemorySize, 105472);
    cudaFuncSetAttribute(gemm_head,                   cudaFuncAttributeMaxDynamicSharedMemorySize, SMTOT_H);

    prep_all<<<2978, 256>>>(W0, Ws, W1, bn_g, bn_b, bn_m, bn_v);
    xcvt<<<1024, 256>>>(obs);

    // Layer 0: halo-agg(x) -> g_agg (64-wide, cols>=32 zero); h1 = relu(LN(agg @ W0 + b0))
    agg_halo<32, 64><<<256, 256, 15360>>>(hc);
    gemm_res<64, 80, 20480><<<GRID_P, 256, 56320>>>(agg, w0t, 0, b0, g0, be0, hc + 32);

    // Layers 1..3: halo-agg -> B-resident GEMM + LN
    for (int l = 1; l < 4; l++) {
        agg_halo<256, 256><<<256, 256, 87040>>>(hc + 32 + (l - 1) * 256);
        gemm_res<256, 272, 69632><<<GRID_P, 256, 105472>>>(
            agg, wst + (size_t)(l - 1) * 65536, l,
            bs + (l - 1) * 256, gs + (l - 1) * 256, bes + (l - 1) * 256,
            hc + 32 + l * 256);
    }

    // Head: fused GEMM + BN + ReLU + W2-dot -> g_part (1024 tiles)
    gemm_head<<<GRID_P, 256, SMTOT_H>>>(hc, w1t, b1, W2);

    // Tail: combine + mask + counter reset
    mask_kernel<<<256, 256>>>(obs, b2, out);
}

// round 16
// speedup vs baseline: 1.1642x; 1.1642x over previous
#include <cuda_runtime.h>
#include <cuda_bf16.h>
#include <cuda_fp16.h>

typedef unsigned int u32;
typedef unsigned char u8;
typedef unsigned short u16;

#define ROWS 65536
#define NBSTRIDE 33792
#define MIDB 1088              // padded concat stride (1056 data + 32 zeros)
#define MIN_VAL (-10000000.0f)
#define GRID_P 304

// ---------------- persistent scratch (BSS, zero-init) ----------------
__device__ u8    g_hc [(size_t)ROWS * MIDB];   // fp8: [x(32) | h1..h4 | zeros]
__device__ u8    g_w0t[256 * 64];              // W0^T [N=256][K=64], k>=32 zero
__device__ u8    g_wst[3][256 * 256];          // Ws^T fp8
__device__ u8    g_w1t[(size_t)512 * 1088];    // W1^T fp8, k>=1056 zero
__device__ float g_part[2 * ROWS];             // head partial dots per N-half
__device__ float g_sc[512], g_sh[512];         // folded BN scale/shift
__device__ u32   g_ctr[8];                     // dynamic tile counters

// ---------------- helpers ----------------
__device__ __forceinline__ u32 s2u(const void* p){
    u32 a;
    asm("{ .reg .u64 t; cvta.to.shared.u64 t, %1; cvt.u32.u64 %0, t; }" : "=r"(a) : "l"(p));
    return a;
}
__device__ __forceinline__ void cpa16(u32 dst, const void* src){
    asm volatile("cp.async.cg.shared.global [%0], [%1], 16;" :: "r"(dst), "l"(src));
}
#define CP_COMMIT() asm volatile("cp.async.commit_group;" ::: "memory")
#define CP_WAIT(n)  asm volatile("cp.async.wait_group %0;" :: "n"(n) : "memory")

__device__ __forceinline__ void mma_fp8_h(u32* c, const u32* a, u32 b0, u32 b1){
    asm volatile("mma.sync.aligned.m16n8k32.row.col.f16.e4m3.e4m3.f16 "
        "{%0,%1}, {%2,%3,%4,%5}, {%6,%7}, {%0,%1};"
        : "+r"(c[0]), "+r"(c[1])
        : "r"(a[0]), "r"(a[1]), "r"(a[2]), "r"(a[3]), "r"(b0), "r"(b1));
}
#define LDSM4(r0, r1, r2, r3, addr) \
    asm volatile("ldmatrix.sync.aligned.m8n8.x4.shared.b16 {%0,%1,%2,%3}, [%4];" \
        : "=r"(r0), "=r"(r1), "=r"(r2), "=r"(r3) : "r"(addr))

__device__ __forceinline__ u16 pk8(float lo, float hi){
    u16 t;
    asm("cvt.rn.satfinite.e4m3x2.f32 %0, %1, %2;" : "=h"(t) : "f"(hi), "f"(lo));
    return t;
}
__device__ __forceinline__ u8 cvt1(float v){ return (u8)(pk8(v, 0.f) & 0xff); }
__device__ __forceinline__ float2 h2f(u32 h){
    return __half22float2(*reinterpret_cast<__half2*>(&h));
}
__device__ __forceinline__ void hacc_fp8x4(u32& a0, u32& a1, u32 v){
    u32 f0, f1;
    asm("cvt.rn.f16x2.e4m3x2 %0, %1;" : "=r"(f0) : "h"((u16)(v & 0xffff)));
    asm("cvt.rn.f16x2.e4m3x2 %0, %1;" : "=r"(f1) : "h"((u16)(v >> 16)));
    asm("add.rn.f16x2 %0, %0, %1;" : "+r"(a0) : "r"(f0));
    asm("add.rn.f16x2 %0, %0, %1;" : "+r"(a1) : "r"(f1));
}
__device__ __forceinline__ u32 pack2h(u32 h0, u32 h1){
    u16 a, b;
    asm("cvt.rn.satfinite.e4m3x2.f16x2 %0, %1;" : "=h"(a) : "r"(h0));
    asm("cvt.rn.satfinite.e4m3x2.f16x2 %0, %1;" : "=h"(b) : "r"(h1));
    return (u32)a | ((u32)b << 16);
}

// ---------------- merged prep kernel ----------------
__global__ void prep_all(const float* __restrict__ W0, const float* __restrict__ Ws,
                         const float* __restrict__ W1,
                         const float* __restrict__ bn_g, const float* __restrict__ bn_b,
                         const float* __restrict__ bn_m, const float* __restrict__ bn_v){
    int blk = blockIdx.x, tid = threadIdx.x;
    if (blk < 32){
        int i = blk * 256 + tid;
        int n = i >> 5, k = i & 31;
        g_w0t[n * 64 + k] = cvt1(W0[k * 256 + n]);
    } else if (blk < 800){
        int i = (blk - 32) * 256 + tid;
        int l = i >> 16, r = i & 65535;
        int n = r >> 8, k = r & 255;
        g_wst[l][n * 256 + k] = cvt1(Ws[l * 65536 + k * 256 + n]);
    } else if (blk < 2976){
        int i = (blk - 800) * 256 + tid;
        int n = i / 1088, k = i - n * 1088;
        g_w1t[i] = (k < 1056) ? cvt1(W1[k * 512 + n]) : (u8)0;
    } else {
        int i = (blk - 2976) * 256 + tid;
        if (i < 512){
            float sc = bn_g[i] * rsqrtf(bn_v[i] + 1e-5f);
            g_sc[i] = sc;
            g_sh[i] = bn_b[i] - bn_m[i] * sc;
        }
    }
}

__global__ void xcvt(const float* __restrict__ obs){
    int q = blockIdx.x * 256 + threadIdx.x;
    int row = q >> 2, j = q & 3;
    int b = row >> 10, n = row & 1023;
    const float4* s = reinterpret_cast<const float4*>(obs + (size_t)b * NBSTRIDE + 1024 + n * 32 + j * 8);
    float4 a = s[0], c = s[1];
    u32 w0 = (u32)pk8(a.x, a.y) | ((u32)pk8(a.z, a.w) << 16);
    u32 w1 = (u32)pk8(c.x, c.y) | ((u32)pk8(c.z, c.w) << 16);
    *reinterpret_cast<uint2*>(g_hc + (size_t)row * MIDB + j * 8) = make_uint2(w0, w1);
}

// ---------------- warp-specialized persistent layer GEMM + fused agg + LN ----------
// 384 thr: warps 0-7 compute (tile 64x256, warp tile 32x64), warps 8-11 producers
// (agg LDG + f16 convert + STS for A, cp.async for B). 3 stages. occ 2.
// SMEM: stages 3 x (A 5120 + B 20480) = 76800; red @76800 (2KB); musd @78848 (512B);
// params @79360 (bias|gamma|beta, 3KB). Total 82432.
#define SMEMP 82432
template<int KFULL, int AW>
__global__ void __launch_bounds__(384, 2)
gemm_lnp(const u8* __restrict__ A, const u8* __restrict__ Bt, int slot,
         const float* __restrict__ bias, const float* __restrict__ gamma,
         const float* __restrict__ beta, u8* __restrict__ outp)
{
    extern __shared__ char sm[];
    __shared__ u32 s_tile;
    const u32 sb = s2u(sm);
    const int tid  = threadIdx.x;
    const int lane = tid & 31, wid = tid >> 5;
    const bool comp = (wid < 8);
    const int wm = wid & 1, wn = (wid >> 1) & 3;
    const int ptid = tid - 256;                    // producer index 0..127
    constexpr int NC = KFULL / 64;

    // cache epilogue params in smem
    float* pPar = reinterpret_cast<float*>(sm + 79360);
    if (tid < 256){
        pPar[tid]       = bias[tid];
        pPar[256 + tid] = gamma[tid];
        pPar[512 + tid] = beta[tid];
    }
    __syncthreads();

    for (;;){
        __syncthreads();
        if (tid == 0) s_tile = atomicAdd(&g_ctr[slot], 1u);
        __syncthreads();
        const u32 t = s_tile;
        if (t >= 1024u) break;
        const int row0 = (int)t << 6;

        // producer lambdas
        const int ar = ptid >> 1;                  // 0..63 (valid when !comp)
        const int arow = row0 + ar;
        const int an = arow & 1023, agr = an >> 5, agc = an & 31;

        auto fillA = [&](int kc, int stg){
#pragma unroll
            for (int s2 = 0; s2 < 2; s2++){
                int aseg = (ptid & 1) * 2 + s2;
                int colb = kc * 64 + aseg * 16;
                u32 dsto = (u32)stg * 25600u + (u32)(ar * 80 + aseg * 16);
                if (AW != 256 && colb >= AW){
                    *reinterpret_cast<uint4*>(sm + dsto) = make_uint4(0u, 0u, 0u, 0u);
                } else {
                    const u8* base = A + (size_t)arow * MIDB + colb;
                    uint4 r0 = make_uint4(0u,0u,0u,0u), r1 = r0, r2 = r0, r3 = r0;
                    if (agc > 0)  r0 = *reinterpret_cast<const uint4*>(base - MIDB);
                    if (agc < 31) r1 = *reinterpret_cast<const uint4*>(base + MIDB);
                    if (agr > 0)  r2 = *reinterpret_cast<const uint4*>(base - 32 * MIDB);
                    if (agr < 31) r3 = *reinterpret_cast<const uint4*>(base + 32 * MIDB);
                    u32 s[8];
#pragma unroll
                    for (int e = 0; e < 8; e++) s[e] = 0u;
                    hacc_fp8x4(s[0], s[1], r0.x); hacc_fp8x4(s[2], s[3], r0.y);
                    hacc_fp8x4(s[4], s[5], r0.z); hacc_fp8x4(s[6], s[7], r0.w);
                    hacc_fp8x4(s[0], s[1], r1.x); hacc_fp8x4(s[2], s[3], r1.y);
                    hacc_fp8x4(s[4], s[5], r1.z); hacc_fp8x4(s[6], s[7], r1.w);
                    hacc_fp8x4(s[0], s[1], r2.x); hacc_fp8x4(s[2], s[3], r2.y);
                    hacc_fp8x4(s[4], s[5], r2.z); hacc_fp8x4(s[6], s[7], r2.w);
                    hacc_fp8x4(s[0], s[1], r3.x); hacc_fp8x4(s[2], s[3], r3.y);
                    hacc_fp8x4(s[4], s[5], r3.z); hacc_fp8x4(s[6], s[7], r3.w);
                    *reinterpret_cast<uint4*>(sm + dsto) =
                        make_uint4(pack2h(s[0], s[1]), pack2h(s[2], s[3]),
                                   pack2h(s[4], s[5]), pack2h(s[6], s[7]));
                }
            }
        };
        auto fillB = [&](int kc, int stg){
#pragma unroll
            for (int i = 0; i < 8; i++){
                int idx = ptid + 128 * i;           // 1024 segs
                int n = idx >> 2, seg = idx & 3;
                cpa16(sb + (u32)stg * 25600u + 5120u + (u32)(n * 80 + seg * 16),
                      Bt + (size_t)n * KFULL + kc * 64 + seg * 16);
            }
        };

        // prologue: producers fill stages 0[,1]
        if (!comp){
            fillA(0, 0); fillB(0, 0); CP_COMMIT();
            if (NC > 1){ fillA(1, 1); fillB(1, 1); CP_COMMIT(); CP_WAIT(1); }
            else CP_WAIT(0);
        }
        __syncthreads();                            // stage 0 ready

        u32 acc[2][8][2];
        if (comp){
#pragma unroll
            for (int mt = 0; mt < 2; mt++)
#pragma unroll
                for (int nt = 0; nt < 8; nt++){ acc[mt][nt][0] = 0u; acc[mt][nt][1] = 0u; }
        }

        for (int kc = 0; kc < NC; kc++){
            if (comp){
                const u32 Ab = sb + (u32)(kc % 3) * 25600u;
                const u32 Bb = Ab + 5120u;
#pragma unroll
                for (int s = 0; s < 2; s++){
                    u32 a0[4], a1[4];
                    {
                        u32 addr = Ab + (u32)((wm * 32 + (lane & 7) + ((lane >> 3) & 1) * 8) * 80
                                              + s * 32 + (lane >> 4) * 16);
                        LDSM4(a0[0], a0[1], a0[2], a0[3], addr);
                        LDSM4(a1[0], a1[1], a1[2], a1[3], addr + 16 * 80);
                    }
#pragma unroll
                    for (int np = 0; np < 4; np++){
                        u32 b0, b1, b2, b3;
                        u32 addr = Bb + (u32)((wn * 64 + (np * 2 + (lane >> 4)) * 8 + (lane & 7)) * 80
                                              + s * 32 + ((lane >> 3) & 1) * 16);
                        LDSM4(b0, b1, b2, b3, addr);
                        mma_fp8_h(acc[0][np * 2],     a0, b0, b1);
                        mma_fp8_h(acc[0][np * 2 + 1], a0, b2, b3);
                        mma_fp8_h(acc[1][np * 2],     a1, b0, b1);
                        mma_fp8_h(acc[1][np * 2 + 1], a1, b2, b3);
                    }
                }
            } else {
                if (kc + 2 < NC){
                    int stg2 = (kc + 2) % 3;
                    fillA(kc + 2, stg2); fillB(kc + 2, stg2);
                }
                CP_COMMIT();
                CP_WAIT(1);                         // stage kc+1 B resident
            }
            __syncthreads();
        }

        // ---- LN epilogue (two passes; params from smem) ----
        const int cbase = wn * 64 + (lane & 3) * 2;
        float s1[2][2], s2[2][2];
        if (comp){
#pragma unroll
            for (int mt = 0; mt < 2; mt++){ s1[mt][0]=0.f; s1[mt][1]=0.f; s2[mt][0]=0.f; s2[mt][1]=0.f; }
#pragma unroll
            for (int mt = 0; mt < 2; mt++)
#pragma unroll
                for (int nt = 0; nt < 8; nt++){
                    int c = cbase + nt * 8;
                    float b0 = pPar[c], b1v = pPar[c + 1];
                    float2 p0 = h2f(acc[mt][nt][0]);
                    float2 p1 = h2f(acc[mt][nt][1]);
                    float v0 = p0.x + b0, v1 = p0.y + b1v;
                    float v2 = p1.x + b0, v3 = p1.y + b1v;
                    s1[mt][0] += v0 + v1; s2[mt][0] = fmaf(v0, v0, fmaf(v1, v1, s2[mt][0]));
                    s1[mt][1] += v2 + v3; s2[mt][1] = fmaf(v2, v2, fmaf(v3, v3, s2[mt][1]));
                }
#pragma unroll
            for (int o = 1; o <= 2; o <<= 1)
#pragma unroll
                for (int mt = 0; mt < 2; mt++)
#pragma unroll
                    for (int h = 0; h < 2; h++){
                        s1[mt][h] += __shfl_xor_sync(0xffffffffu, s1[mt][h], o);
                        s2[mt][h] += __shfl_xor_sync(0xffffffffu, s2[mt][h], o);
                    }
            float2* red = reinterpret_cast<float2*>(sm + 76800);
            if ((lane & 3) == 0){
#pragma unroll
                for (int mt = 0; mt < 2; mt++)
#pragma unroll
                    for (int h = 0; h < 2; h++){
                        int r = wm * 32 + mt * 16 + (lane >> 2) + 8 * h;
                        red[r * 4 + wn] = make_float2(s1[mt][h], s2[mt][h]);
                    }
            }
        }
        __syncthreads();
        {
            float2* red  = reinterpret_cast<float2*>(sm + 76800);
            float2* musd = reinterpret_cast<float2*>(sm + 78848);
            if (tid < 64){
                float S1 = 0.f, S2 = 0.f;
#pragma unroll
                for (int w = 0; w < 4; w++){ float2 v = red[tid * 4 + w]; S1 += v.x; S2 += v.y; }
                float mu = S1 * (1.f / 256.f);
                float rstd = rsqrtf(fmaf(-mu, mu, S2 * (1.f / 256.f)) + 1e-5f);
                musd[tid] = make_float2(mu, rstd);
            }
        }
        __syncthreads();
        if (comp){
            float2* musd = reinterpret_cast<float2*>(sm + 78848);
#pragma unroll
            for (int mt = 0; mt < 2; mt++)
#pragma unroll
                for (int h = 0; h < 2; h++){
                    int r = wm * 32 + mt * 16 + (lane >> 2) + 8 * h;
                    float2 ms = musd[r];
                    u8* orow = outp + (size_t)(row0 + r) * MIDB;
#pragma unroll
                    for (int nt = 0; nt < 8; nt++){
                        int c = cbase + nt * 8;
                        float2 p = (h == 0) ? h2f(acc[mt][nt][0]) : h2f(acc[mt][nt][1]);
                        float v0 = p.x + pPar[c];
                        float v1 = p.y + pPar[c + 1];
                        float o0 = fmaxf(fmaf((v0 - ms.x) * ms.y, pPar[256 + c],     pPar[512 + c]),     0.f);
                        float o1 = fmaxf(fmaf((v1 - ms.x) * ms.y, pPar[256 + c + 1], pPar[512 + c + 1]), 0.f);
                        *reinterpret_cast<u16*>(orow + c) = pk8(o0, o1);
                    }
                }
        }
    }
}

// ---------------- head: tile 128x256, 3-stage, fused BN/ReLU/W2 (R13, proven) ----
#define SMTOT_H 92160
__global__ void __launch_bounds__(256, 2)
gemm_head(const u8* __restrict__ A, const u8* __restrict__ Bt,
          const float* __restrict__ b1, const float* __restrict__ W2)
{
    extern __shared__ char sm[];
    __shared__ u32 s_tile;
    const u32 sb = s2u(sm);
    const int tid  = threadIdx.x;
    const int lane = tid & 31, wid = tid >> 5;
    const int wm = wid & 1, wn = wid >> 1;
    constexpr int NC = 17;

    for (;;){
        __syncthreads();
        if (tid == 0) s_tile = atomicAdd(&g_ctr[4], 1u);
        __syncthreads();
        const u32 t = s_tile;
        if (t >= 1024u) break;

        const int row0  = (int)(t >> 1) << 7;
        const int ncol0 = (int)(t & 1) << 8;
        const u8* Bp = Bt + (size_t)ncol0 * 1088;

        auto cpA = [&](int kc, int stg){
#pragma unroll
            for (int i = 0; i < 2; i++){
                int q = tid + 256 * i;
                int r = q >> 2, seg = q & 3;
                cpa16(sb + (u32)stg * 30720u + (u32)(r * 80 + seg * 16),
                      A + (size_t)(row0 + r) * MIDB + kc * 64 + seg * 16);
            }
        };
        auto cpB = [&](int kc, int stg){
#pragma unroll
            for (int i = 0; i < 4; i++){
                int q = tid + 256 * i;
                int n = q >> 2, seg = q & 3;
                cpa16(sb + (u32)stg * 30720u + 10240u + (u32)(n * 80 + seg * 16),
                      Bp + (size_t)n * 1088 + kc * 64 + seg * 16);
            }
        };

        u32 acc[4][8][2];
#pragma unroll
        for (int mt = 0; mt < 4; mt++)
#pragma unroll
            for (int nt = 0; nt < 8; nt++){ acc[mt][nt][0] = 0u; acc[mt][nt][1] = 0u; }

#pragma unroll
        for (int p = 0; p < 2; p++){
            cpA(p, p); cpB(p, p);
            CP_COMMIT();
        }

        for (int kc = 0; kc < NC; kc++){
            if (kc + 2 < NC){
                int stg2 = (kc + 2) % 3;
                cpA(kc + 2, stg2); cpB(kc + 2, stg2);
            }
            CP_COMMIT();
            CP_WAIT(2);
            __syncthreads();

            const u32 Ab = sb + (u32)(kc % 3) * 30720u;
            const u32 Bb = Ab + 10240u;
#pragma unroll
            for (int s = 0; s < 2; s++){
                u32 a[4][4];
#pragma unroll
                for (int mt = 0; mt < 4; mt++){
                    u32 addr = Ab + (u32)((wm * 64 + mt * 16 + (lane & 7) + ((lane >> 3) & 1) * 8) * 80
                                          + s * 32 + (lane >> 4) * 16);
                    LDSM4(a[mt][0], a[mt][1], a[mt][2], a[mt][3], addr);
                }
#pragma unroll
                for (int np = 0; np < 4; np++){
                    u32 b0, b1v, b2, b3;
                    u32 addr = Bb + (u32)((wn * 64 + (np * 2 + (lane >> 4)) * 8 + (lane & 7)) * 80
                                          + s * 32 + ((lane >> 3) & 1) * 16);
                    LDSM4(b0, b1v, b2, b3, addr);
#pragma unroll
                    for (int mt = 0; mt < 4; mt++){
                        mma_fp8_h(acc[mt][np * 2],     a[mt], b0, b1v);
                        mma_fp8_h(acc[mt][np * 2 + 1], a[mt], b2, b3);
                    }
                }
            }
        }
        __syncthreads();

        const int cbase = wn * 64 + (lane & 3) * 2;
        float* part = reinterpret_cast<float*>(sm + 61440);
#pragma unroll
        for (int mt = 0; mt < 4; mt++)
#pragma unroll
            for (int h = 0; h < 2; h++){
                int r = wm * 64 + mt * 16 + (lane >> 2) + 8 * h;
                float s = 0.f;
#pragma unroll
                for (int nt = 0; nt < 8; nt++){
                    int c  = cbase + nt * 8;
                    int gc = ncol0 + c;
                    float2 p = (h == 0) ? h2f(acc[mt][nt][0]) : h2f(acc[mt][nt][1]);
                    float v0 = p.x + __ldg(b1 + gc);
                    float v1 = p.y + __ldg(b1 + gc + 1);
                    float t0 = fmaxf(fmaf(v0, g_sc[gc],     g_sh[gc]),     0.f);
                    float t1 = fmaxf(fmaf(v1, g_sc[gc + 1], g_sh[gc + 1]), 0.f);
                    s = fmaf(t0, __ldg(W2 + gc), s);
                    s = fmaf(t1, __ldg(W2 + gc + 1), s);
                }
                s += __shfl_xor_sync(0xffffffffu, s, 1);
                s += __shfl_xor_sync(0xffffffffu, s, 2);
                if ((lane & 3) == 0) part[r * 4 + wn] = s;
            }
        __syncthreads();
        if (tid < 128){
            float S = part[tid * 4] + part[tid * 4 + 1] + part[tid * 4 + 2] + part[tid * 4 + 3];
            g_part[(size_t)(t & 1) * ROWS + row0 + tid] = S;
        }
    }
}

// ---------------- tail: combine partials, +b2, mask; reset counters ----------------
__global__ void mask_kernel(const float* __restrict__ obs, const float* __restrict__ b2,
                            float* __restrict__ out){
    int idx = blockIdx.x * 256 + threadIdx.x;
    int b = idx >> 10, n = idx & 1023;
    float y = g_part[idx] + g_part[ROWS + idx] + b2[0];
    out[idx] = (obs[(size_t)b * NBSTRIDE + n] != 0.f) ? y : MIN_VAL;
    if (idx < 8) g_ctr[idx] = 0u;
}

// ---------------- launch ----------------
extern "C" void kernel_launch(void* const* d_in, const int* in_sizes, int n_in,
                              void* d_out, int out_size) {
    const float* obs  = (const float*)d_in[0];
    const float* W0   = (const float*)d_in[3];
    const float* b0   = (const float*)d_in[4];
    const float* g0   = (const float*)d_in[5];
    const float* be0  = (const float*)d_in[6];
    const float* Ws   = (const float*)d_in[7];
    const float* bs   = (const float*)d_in[8];
    const float* gs   = (const float*)d_in[9];
    const float* bes  = (const float*)d_in[10];
    const float* W1   = (const float*)d_in[11];
    const float* b1   = (const float*)d_in[12];
    const float* bn_g = (const float*)d_in[13];
    const float* bn_b = (const float*)d_in[14];
    const float* bn_m = (const float*)d_in[15];
    const float* bn_v = (const float*)d_in[16];
    const float* W2   = (const float*)d_in[17];
    const float* b2   = (const float*)d_in[18];
    float* out = (float*)d_out;

    u8 *hc, *w0t, *wst, *w1t;
    cudaGetSymbolAddress((void**)&hc,  g_hc);
    cudaGetSymbolAddress((void**)&w0t, g_w0t);
    cudaGetSymbolAddress((void**)&wst, g_wst);
    cudaGetSymbolAddress((void**)&w1t, g_w1t);

    cudaFuncSetAttribute(gemm_lnp<64,  32 >, cudaFuncAttributeMaxDynamicSharedMemorySize, SMEMP);
    cudaFuncSetAttribute(gemm_lnp<256, 256>, cudaFuncAttributeMaxDynamicSharedMemorySize, SMEMP);
    cudaFuncSetAttribute(gemm_head,          cudaFuncAttributeMaxDynamicSharedMemorySize, SMTOT_H);

    prep_all<<<2978, 256>>>(W0, Ws, W1, bn_g, bn_b, bn_m, bn_v);
    xcvt<<<1024, 256>>>(obs);

    // Layer 0: h1 = relu(LN(agg(x) @ W0 + b0)), producer-warp fused agg
    gemm_lnp<64, 32><<<GRID_P, 384, SMEMP>>>(hc, w0t, 0, b0, g0, be0, hc + 32);

    // Layers 1..3
    for (int l = 1; l < 4; l++) {
        gemm_lnp<256, 256><<<GRID_P, 384, SMEMP>>>(
            hc + 32 + (l - 1) * 256, wst + (size_t)(l - 1) * 65536, l,
            bs + (l - 1) * 256, gs + (l - 1) * 256, bes + (l - 1) * 256,
            hc + 32 + l * 256);
    }

    // Head: fused GEMM + BN + ReLU + W2-dot -> g_part
    gemm_head<<<GRID_P, 256, SMTOT_H>>>(hc, w1t, b1, W2);

    // Tail: combine + mask + counter reset
    mask_kernel<<<256, 256>>>(obs, b2, out);
}